// round 9
// baseline (speedup 1.0000x reference)
#include <cuda_runtime.h>
#include <math.h>

#define K_VOX 40000
#define T_PTS 35
#define C_IN  7
#define U1    16
#define U2    32
#define DD    10
#define HH    400
#define WW    352
#define NROWS (K_VOX * T_PTS)
#define EPSBN 1e-5f
#define H1S   20            // h1 row stride (floats), 16B-aligned rows
#define VW    8             // warps (voxels) per block

// ---------------- global scratch (static, allocation-free) ----------------
__device__ float g_sum1[U1], g_sq1[U1];
__device__ float g_sum2[U2], g_sq2[U2];
__device__ float g_vox[(size_t)K_VOX * 4 * U2];  // [v][{Mx,Mn,Mx1,Mn1}][32]
__device__ int   g_flags[K_VOX];                 // bit0 anyM, bit1 allM

// ---------------- host-side fork/join resources (static init, no device mem) ----
namespace {
struct HostCtx {
    cudaStream_t s2;
    cudaEvent_t  ev_fork, ev_join;
    HostCtx() {
        cudaStreamCreateWithFlags(&s2, cudaStreamNonBlocking);
        cudaEventCreateWithFlags(&ev_fork, cudaEventDisableTiming);
        cudaEventCreateWithFlags(&ev_join, cudaEventDisableTiming);
    }
};
HostCtx g_ctx;
}

__global__ void reset_kernel() {
    int t = threadIdx.x;
    if (t < U1) { g_sum1[t] = 0.f; g_sq1[t] = 0.f; }
    if (t < U2) { g_sum2[t] = 0.f; g_sq2[t] = 0.f; }
}

// ---------------- pass 1: BN1 statistics ----------------
__global__ void __launch_bounds__(256)
stats1_kernel(const float* __restrict__ feat,
              const float* __restrict__ w1,
              const float* __restrict__ b1) {
    __shared__ float sw[C_IN * U1];
    __shared__ float sb[U1];
    __shared__ float ssum[U1], ssq[U1];
    int tid = threadIdx.x;
    if (tid < C_IN * U1) sw[tid] = w1[tid];
    if (tid < U1) { sb[tid] = b1[tid]; ssum[tid] = 0.f; ssq[tid] = 0.f; }
    __syncthreads();

    float psum[U1], psq[U1];
#pragma unroll
    for (int u = 0; u < U1; u++) { psum[u] = 0.f; psq[u] = 0.f; }

    for (int r = blockIdx.x * blockDim.x + tid; r < NROWS;
         r += gridDim.x * blockDim.x) {
        const float* fp = feat + (size_t)r * C_IN;
        float f[C_IN];
#pragma unroll
        for (int c = 0; c < C_IN; c++) f[c] = fp[c];
#pragma unroll
        for (int u = 0; u < U1; u++) {
            float a = sb[u];
#pragma unroll
            for (int c = 0; c < C_IN; c++) a = fmaf(f[c], sw[c * U1 + u], a);
            a = fmaxf(a, 0.f);
            psum[u] += a;
            psq [u]  = fmaf(a, a, psq[u]);
        }
    }
#pragma unroll
    for (int u = 0; u < U1; u++) {
#pragma unroll
        for (int o = 16; o > 0; o >>= 1) {
            psum[u] += __shfl_down_sync(0xFFFFFFFFu, psum[u], o);
            psq [u] += __shfl_down_sync(0xFFFFFFFFu, psq [u], o);
        }
        if ((tid & 31) == 0) { atomicAdd(&ssum[u], psum[u]); atomicAdd(&ssq[u], psq[u]); }
    }
    __syncthreads();
    if (tid < U1) {
        atomicAdd(&g_sum1[tid], ssum[tid]);
        atomicAdd(&g_sq1 [tid], ssq [tid]);
    }
}

// ---------------- pass 2: voxel pass, high occupancy (4 blocks/SM) ----------
__global__ void __launch_bounds__(VW * 32, 4)   // <=64 regs -> 32 warps/SM
voxel_kernel(const float* __restrict__ feat,
             const float* __restrict__ g1,  const float* __restrict__ be1,
             const float* __restrict__ w1,  const float* __restrict__ b1,
             const float* __restrict__ w2,  const float* __restrict__ b2) {
    __shared__ float sw1[C_IN * U1];
    __shared__ float sb1[U1];
    __shared__ float s_sc1[U1], s_sh1[U1], s_h1z[U1];
    __shared__ float s_h1[VW][T_PTS][H1S];
    __shared__ float s_agg[VW][U1];
    __shared__ float bsum[U2], bsq[U2];

    const int tid  = threadIdx.x;
    const int w    = tid >> 5;
    const int lane = tid & 31;
    const float invN = 1.0f / (float)NROWS;

    if (tid < C_IN * U1) sw1[tid] = w1[tid];
    if (tid < U2) { bsum[tid] = 0.f; bsq[tid] = 0.f; }
    if (tid < U1) {
        sb1[tid] = b1[tid];
        float mean = __ldcg(&g_sum1[tid]) * invN;
        float var  = __ldcg(&g_sq1 [tid]) * invN - mean * mean;
        float sc   = rsqrtf(var + EPSBN) * g1[tid];
        s_sc1[tid] = sc;
        float sh   = be1[tid] - mean * sc;
        s_sh1[tid] = sh;
        s_h1z[tid] = fmaf(fmaxf(b1[tid], 0.f), sc, sh);
    }
    __syncthreads();

    const float b2l = b2[lane];
    const float h2z = fmaxf(b2l, 0.f);

    const int v = blockIdx.x * VW + w;   // grid covers K_VOX exactly
    const float* fv = feat + (size_t)v * T_PTS * C_IN;

    unsigned mb0, mb1;
    {   // rows t = lane (32 valid)
        const float* fp = fv + lane * C_IN;
        float f[C_IN]; float mx = -INFINITY;
#pragma unroll
        for (int c = 0; c < C_IN; c++) { f[c] = fp[c]; mx = fmaxf(mx, f[c]); }
        bool msk = (mx != 0.0f);
        mb0 = __ballot_sync(0xFFFFFFFFu, msk);
        if (msk) {
            int rank = __popc(mb0 & ((1u << lane) - 1u));
            float4* row = (float4*)&s_h1[w][rank][0];
#pragma unroll
            for (int half = 0; half < 2; half++) {
                float h[8];
#pragma unroll
                for (int uu = 0; uu < 8; uu++) {
                    int u = half * 8 + uu;
                    float a = sb1[u];
#pragma unroll
                    for (int c = 0; c < C_IN; c++) a = fmaf(f[c], sw1[c * U1 + u], a);
                    h[uu] = fmaf(fmaxf(a, 0.f), s_sc1[u], s_sh1[u]);
                }
                row[half * 2 + 0] = make_float4(h[0], h[1], h[2], h[3]);
                row[half * 2 + 1] = make_float4(h[4], h[5], h[6], h[7]);
            }
        }
    }
    {   // rows t = 32 + lane (3 valid)
        bool act = (lane < (T_PTS - 32));
        float f[C_IN]; float mx = -INFINITY;
        if (act) {
            const float* fp = fv + (32 + lane) * C_IN;
#pragma unroll
            for (int c = 0; c < C_IN; c++) { f[c] = fp[c]; mx = fmaxf(mx, f[c]); }
        }
        bool msk = act && (mx != 0.0f);
        mb1 = __ballot_sync(0xFFFFFFFFu, msk);
        if (msk) {
            int rank = __popc(mb0) + __popc(mb1 & ((1u << lane) - 1u));
            float4* row = (float4*)&s_h1[w][rank][0];
#pragma unroll
            for (int half = 0; half < 2; half++) {
                float h[8];
#pragma unroll
                for (int uu = 0; uu < 8; uu++) {
                    int u = half * 8 + uu;
                    float a = sb1[u];
#pragma unroll
                    for (int c = 0; c < C_IN; c++) a = fmaf(f[c], sw1[c * U1 + u], a);
                    h[uu] = fmaf(fmaxf(a, 0.f), s_sc1[u], s_sh1[u]);
                }
                row[half * 2 + 0] = make_float4(h[0], h[1], h[2], h[3]);
                row[half * 2 + 1] = make_float4(h[4], h[5], h[6], h[7]);
            }
        }
    }
    const int nm = __popc(mb0) + __popc(mb1);
    const int nz = T_PTS - nm;
    __syncwarp();

    if (lane < U1) {
        float mx = (nz > 0) ? s_h1z[lane] : -INFINITY;
        for (int r = 0; r < nm; r++) mx = fmaxf(mx, s_h1[w][r][lane]);
        s_agg[w][lane] = mx;
    }
    __syncwarp();

    // aggdot (bias folded); w2 agg-half via transient __ldg
    float aggdot = b2l;
#pragma unroll
    for (int j = 0; j < U1; j++)
        aggdot = fmaf(s_agg[w][j], __ldg(&w2[(U1 + j) * U2 + lane]), aggdot);

    float wcol[U1];
#pragma unroll
    for (int i = 0; i < U1; i++) wcol[i] = w2[i * U2 + lane];

    float vsum, vsq;
    {
        float fz = (float)nz;
        vsum = fz * h2z;
        vsq  = fz * h2z * h2z;
    }
    float Mx1 = -INFINITY, Mn1 = INFINITY;

    for (int r = 0; r < nm; r++) {
        const float4* row = (const float4*)&s_h1[w][r][0];
        float4 a0 = row[0], a1 = row[1];
        float d0 = fmaf(a0.x, wcol[0], 0.f), d1 = fmaf(a0.y, wcol[1], 0.f);
        d0 = fmaf(a0.z, wcol[2],  d0); d1 = fmaf(a0.w, wcol[3],  d1);
        d0 = fmaf(a1.x, wcol[4],  d0); d1 = fmaf(a1.y, wcol[5],  d1);
        d0 = fmaf(a1.z, wcol[6],  d0); d1 = fmaf(a1.w, wcol[7],  d1);
        float4 a2 = row[2], a3 = row[3];
        d0 = fmaf(a2.x, wcol[8],  d0); d1 = fmaf(a2.y, wcol[9],  d1);
        d0 = fmaf(a2.z, wcol[10], d0); d1 = fmaf(a2.w, wcol[11], d1);
        d0 = fmaf(a3.x, wcol[12], d0); d1 = fmaf(a3.y, wcol[13], d1);
        d0 = fmaf(a3.z, wcol[14], d0); d1 = fmaf(a3.w, wcol[15], d1);
        float h2 = fmaxf(d0 + d1 + aggdot, 0.f);
        vsum += h2;
        vsq   = fmaf(h2, h2, vsq);
        Mx1 = fmaxf(Mx1, h2);
        Mn1 = fminf(Mn1, h2);
    }
    float Mx = (nz > 0) ? fmaxf(Mx1, h2z) : Mx1;
    float Mn = (nz > 0) ? fminf(Mn1, h2z) : Mn1;

    float* gv = g_vox + (size_t)v * (4 * U2);
    gv[lane]          = Mx;
    gv[U2 + lane]     = Mn;
    gv[2 * U2 + lane] = Mx1;
    gv[3 * U2 + lane] = Mn1;
    if (lane == 0) g_flags[v] = ((nm > 0) ? 1 : 0) | ((nm == T_PTS) ? 2 : 0);

    // BN2 stats: block reduce then one atomic per channel
    atomicAdd(&bsum[lane], vsum);
    atomicAdd(&bsq [lane], vsq);
    __syncthreads();
    if (tid < U2) {
        atomicAdd(&g_sum2[tid], bsum[tid]);
        atomicAdd(&g_sq2 [tid], bsq [tid]);
    }
}

// ---------------- pass 3: finalize BN2 + scatter ----------------
__global__ void __launch_bounds__(256)
scatter_kernel(const float* __restrict__ g2, const float* __restrict__ be2,
               const int* __restrict__ coord, float* __restrict__ out) {
    __shared__ float s_sc2[U2], s_sh2[U2];
    const int tid  = threadIdx.x;
    const int w    = tid >> 5;
    const int lane = tid & 31;
    const float invN = 1.0f / (float)NROWS;

    if (tid < U2) {
        float mean = g_sum2[tid] * invN;
        float var  = g_sq2 [tid] * invN - mean * mean;
        float sc   = rsqrtf(var + EPSBN) * g2[tid];
        s_sc2[tid] = sc;
        s_sh2[tid] = be2[tid] - mean * sc;
    }
    __syncthreads();

    const float sc = s_sc2[lane];
    const float sh = s_sh2[lane];
    const int v = blockIdx.x * 8 + w;   // grid covers K_VOX exactly

    const float* gv = g_vox + (size_t)v * (4 * U2);
    float Mx  = __ldcg(gv + lane);
    float Mn  = __ldcg(gv + U2 + lane);
    float Mx1 = __ldcg(gv + 2 * U2 + lane);
    float Mn1 = __ldcg(gv + 3 * U2 + lane);
    int   fl  = g_flags[v];
    bool anyM = (fl & 1) != 0;
    bool allM = (fl & 2) != 0;

    float agg2 = fmaf((sc >= 0.f) ? Mx  : Mn,  sc, sh);
    float mskd = fmaf((sc >= 0.f) ? Mx1 : Mn1, sc, sh);

    float vwlo = anyM ? mskd : -INFINITY;
    float vwhi = anyM ? agg2 : -INFINITY;
    if (!allM) { vwlo = fmaxf(vwlo, 0.f); vwhi = fmaxf(vwhi, 0.f); }

    const int* cp = coord + (size_t)v * 4;
    size_t base = ((((size_t)cp[0] * DD + cp[1]) * HH + cp[2]) * WW + cp[3]) * (size_t)(2 * U2);
    atomicAdd(out + base + lane,      vwlo);
    atomicAdd(out + base + U2 + lane, vwhi);
}

// ---------------- launch ----------------
extern "C" void kernel_launch(void* const* d_in, const int* in_sizes, int n_in,
                              void* d_out, int out_size) {
    const float* feat  = (const float*)d_in[0];
    const float* w1    = (const float*)d_in[1];
    const float* b1    = (const float*)d_in[2];
    const float* g1    = (const float*)d_in[3];
    const float* be1   = (const float*)d_in[4];
    const float* w2    = (const float*)d_in[5];
    const float* b2    = (const float*)d_in[6];
    const float* g2    = (const float*)d_in[7];
    const float* be2   = (const float*)d_in[8];
    const int*   coord = (const int*)  d_in[9];
    float* out = (float*)d_out;

    // fork: single full-size driver memset, concurrent with the compute chain
    cudaEventRecord(g_ctx.ev_fork, 0);
    cudaStreamWaitEvent(g_ctx.s2, g_ctx.ev_fork, 0);
    cudaMemsetAsync(d_out, 0, (size_t)out_size * sizeof(float), g_ctx.s2);
    cudaEventRecord(g_ctx.ev_join, g_ctx.s2);

    // compute chain (short, high occupancy)
    reset_kernel<<<1, 64>>>();
    stats1_kernel<<<1184, 256>>>(feat, w1, b1);
    voxel_kernel<<<K_VOX / VW, VW * 32>>>(feat, g1, be1, w1, b1, w2, b2);

    // join: scatter needs the zeroed grid + voxel results
    cudaStreamWaitEvent(0, g_ctx.ev_join, 0);
    scatter_kernel<<<K_VOX / 8, 256>>>(g2, be2, coord, out);
}